// round 17
// baseline (speedup 1.0000x reference)
#include <cuda_runtime.h>
#include <cuda_fp16.h>
#include <cstdint>

#define C_IN   128
#define C_OUT  256
#define HW     56
#define IMG    3136
#define NIMG   32
#define KTOT   1152          /* 9 taps * 128 ic */
#define ROWB   144           /* smem row stride: 128B data + 16B skew */

#define TH     8             /* output rows per CTA */
#define TW     32            /* output cols per CTA (w padded to 64: 2 tiles) */
#define EXTW   34            /* TW + 2 halo */
#define EXTH   10            /* TH + 2 halo */
#define EXTROWS (EXTH * EXTW)   /* 340 */

// ---------------- device scratch (alloc-free) ----------------
__device__ __half g_xh[(size_t)NIMG * IMG * C_IN];   // NHWC fp16
__device__ __half g_wh[C_OUT * KTOT];                // [oc][tap][ic] fp16

// ---------------- PTX helpers (base PTX, OK on sm_103) ----------------
__device__ __forceinline__ uint32_t smem_u32(const void* p) {
    return (uint32_t)__cvta_generic_to_shared(p);
}
#define CP16(dst, src, sz) \
    asm volatile("cp.async.cg.shared.global [%0], [%1], 16, %2;" \
                 :: "r"(dst), "l"(src), "r"(sz))
#define CP_COMMIT() asm volatile("cp.async.commit_group;" ::: "memory")

#define LDSM4(r0, r1, r2, r3, a) \
    asm volatile("ldmatrix.sync.aligned.m8n8.x4.shared.b16 {%0,%1,%2,%3}, [%4];" \
                 : "=r"(r0), "=r"(r1), "=r"(r2), "=r"(r3) : "r"(a))

#define MMA(d, a, b) \
    asm volatile("mma.sync.aligned.m16n8k16.row.col.f32.f16.f16.f32 " \
                 "{%0,%1,%2,%3}, {%4,%5,%6,%7}, {%8,%9}, {%0,%1,%2,%3};" \
                 : "+f"((d)[0]), "+f"((d)[1]), "+f"((d)[2]), "+f"((d)[3]) \
                 : "r"((a)[0]), "r"((a)[1]), "r"((a)[2]), "r"((a)[3]), \
                   "r"((b)[0]), "r"((b)[1]))

// Fragment load for one k16 step (A: 4 mt tiles, B: 4 ldsm covering 8 nt tiles)
#define LOAD_FRAGS(A_, B_, k0_) do { \
    _Pragma("unroll") \
    for (int mt = 0; mt < 4; ++mt) \
        LDSM4((A_)[mt][0], (A_)[mt][1], (A_)[mt][2], (A_)[mt][3], \
              aP + mt * 16 * ROWB + (k0_) * 32); \
    _Pragma("unroll") \
    for (int p = 0; p < 4; ++p) \
        LDSM4((B_)[p][0], (B_)[p][1], (B_)[p][2], (B_)[p][3], \
              bP + (uint32_t)((((p >> 1) * EXTW + (p & 1) * 16) * ROWB)) + (k0_) * 32); \
} while (0)

#define DO_MMAS(A_, B_) do { \
    _Pragma("unroll") \
    for (int mt = 0; mt < 4; ++mt) \
        _Pragma("unroll") \
        for (int nt = 0; nt < 8; ++nt) { \
            uint32_t* bf = &(B_)[nt >> 1][(nt & 1) * 2]; \
            MMA(acc[mt][nt], (A_)[mt], bf); \
        } \
} while (0)

// ---------------- SMEM layout ----------------
#define SA_BYTES (128 * ROWB)          /* 18432 */
#define SB_BYTES (EXTROWS * ROWB)      /* 48960 */
#define SA_OFF(b) ((b) * SA_BYTES)
#define SB_OFF(i) (3 * SA_BYTES + (i) * SB_BYTES)
#define SMEM_TOTAL (3 * SA_BYTES + 2 * SB_BYTES)   /* 153216 */

// ---------------- fused prep kernel ----------------
#define XBLKS 1792
#define WBLKS 1152
__global__ void prep_kernel(const float* __restrict__ x, const float* __restrict__ w) {
    const int blk = blockIdx.x, tid = threadIdx.x;
    if (blk < XBLKS) {
        __shared__ float t[C_IN][HW + 1];
        const int b = blk / HW, h = blk - (blk / HW) * HW;
        const float* src = x + ((size_t)b * C_IN) * IMG + h * HW;
        for (int i = tid; i < C_IN * HW; i += 256) {
            int ic = i / HW, ww = i - ic * HW;
            t[ic][ww] = src[(size_t)ic * IMG + ww];
        }
        __syncthreads();
        const size_t ob = ((size_t)(b * HW + h) * HW) * C_IN;
        for (int i = tid; i < HW * 16; i += 256) {
            const int ww = i >> 4, grp = (i & 15) * 8;
            __half h8[8];
            #pragma unroll
            for (int e = 0; e < 8; ++e) h8[e] = __float2half(t[grp + e][ww]);
            *(uint4*)&g_xh[ob + (size_t)ww * C_IN + grp] = *(uint4*)h8;
        }
    } else {
        int i = (blk - XBLKS) * 256 + tid;
        if (i < C_OUT * KTOT) {
            int oc = i / KTOT;
            int r = i - oc * KTOT;
            int tap = r >> 7, ic = r & 127;
            g_wh[i] = __float2half(w[(oc * C_IN + ic) * 9 + tap]);
        }
    }
}

// ---------------- main MMA kernel ----------------
// CTA: 128 oc x 256 pix (8h x 32w of one image). 256 thr, 8 warps 2(m) x 4(n).
// Explicit frag double-buffering: LDSM of k0+1 issued before MMAs of k0 so the
// smem crossbar time hides under the tensor pipe.
__global__ __launch_bounds__(256, 1)
void conv_mma_kernel(const float* __restrict__ bias, float* __restrict__ out) {
    extern __shared__ char smem[];
    const uint32_t sb = smem_u32(smem);
    const int tid = threadIdx.x;
    const int bx  = blockIdx.x;
    const int img = bx / 14;
    const int rr  = bx - img * 14;
    const int h0  = (rr >> 1) * TH;
    const int w0  = (rr & 1) * TW;
    const int ocBase = blockIdx.y * 128;

    // ---- loaders (256 threads) ----
    auto load_A = [&](int tap, int ich, int buf) {
        #pragma unroll
        for (int t = 0; t < 4; ++t) {
            const int i = tid + t * 256;           // 1024 slots: 128 rows x 8 chunks
            const int row = i >> 3, ch = i & 7;
            const char* g = (const char*)(g_wh + (size_t)(ocBase + row) * KTOT
                                          + tap * C_IN + (ich << 6)) + ch * 16;
            const uint32_t d = sb + SA_OFF(buf) + (uint32_t)row * ROWB + ch * 16;
            CP16(d, g, 16);
        }
    };
    auto load_B = [&](int ich) {
        const size_t ibase = (size_t)img * IMG;
        for (int i = tid; i < EXTROWS * 8; i += 256) {     // 2720 slots
            const int row = i >> 3, ch = i & 7;
            const int eh = row / EXTW, ew = row - eh * EXTW;
            const int ih = h0 - 1 + eh, iw = w0 - 1 + ew;
            const bool ok = ((unsigned)ih < (unsigned)HW) && ((unsigned)iw < (unsigned)HW);
            const size_t gi = ok ? ((ibase + ih * HW + iw) * C_IN + (ich << 6)) : 0;
            const char* g = (const char*)(g_xh + gi) + ch * 16;
            const uint32_t d = sb + SB_OFF(ich) + (uint32_t)row * ROWB + ch * 16;
            CP16(d, g, ok ? 16 : 0);
        }
    };

    // ---- compute geometry ----
    const int wid = tid >> 5, lane = tid & 31;
    const int warp_m = wid >> 2;          // 0..1 -> 64 oc rows
    const int warp_n = wid & 3;           // 0..3 -> 64 pix (2 dh x 32 dw)
    const uint32_t aLane =
        (uint32_t)(warp_m * 64 + (lane & 15)) * ROWB + (lane >> 4) * 16;
    const uint32_t bLane =
        (uint32_t)(((lane >> 4) & 1) * 8 + (lane & 7)) * ROWB + ((lane >> 3) & 1) * 16;

    float acc[4][8][4];
    #pragma unroll
    for (int i = 0; i < 4; ++i)
        #pragma unroll
        for (int j = 0; j < 8; ++j)
            #pragma unroll
            for (int e = 0; e < 4; ++e) acc[i][j][e] = 0.f;

    // ---- prologue: g0={B0,A0}, g1={A1}, g2={B1} ----
    load_B(0); load_A(0, 0, 0); CP_COMMIT();
    load_A(1, 0, 1);            CP_COMMIT();
    load_B(1);                  CP_COMMIT();

    int s = 0;
    int pf_tap = 2, pf_ich = 0;   // next A substage to prefetch (s+2)
    #pragma unroll 1
    for (int ich = 0; ich < 2; ++ich) {
        #pragma unroll 1
        for (int tap = 0; tap < 9; ++tap, ++s) {
            // A_s lives in group: s<2 -> g_s ; s>=2 -> g_{s+1}. Provably-correct waits:
            if (s < 2)       asm volatile("cp.async.wait_group 2;" ::: "memory");
            else if (s < 17) asm volatile("cp.async.wait_group 1;" ::: "memory");
            else             asm volatile("cp.async.wait_group 0;" ::: "memory");
            __syncthreads();   // data for s visible; buffer (s+2)%3 free

            if (s <= 15) {
                load_A(pf_tap, pf_ich, (s + 2) % 3);
                CP_COMMIT();
                if (++pf_tap == 9) { pf_tap = 0; pf_ich = 1; }
            }

            const int tr = tap / 3;
            const int tc = tap - tr * 3;
            const uint32_t aP = sb + SA_OFF(s % 3) + aLane;
            const uint32_t bP = sb + SB_OFF(ich) +
                (uint32_t)((warp_n * 2 + tr) * EXTW + tc) * ROWB + bLane;

            // ---- software-pipelined k16 steps: LDSM k0+1 before MMAs of k0 ----
            uint32_t Af[2][4][4], Bf[2][4][4];
            LOAD_FRAGS(Af[0], Bf[0], 0);
            LOAD_FRAGS(Af[1], Bf[1], 1);
            DO_MMAS(Af[0], Bf[0]);
            LOAD_FRAGS(Af[0], Bf[0], 2);
            DO_MMAS(Af[1], Bf[1]);
            LOAD_FRAGS(Af[1], Bf[1], 3);
            DO_MMAS(Af[0], Bf[0]);
            DO_MMAS(Af[1], Bf[1]);
        }
    }

    // ---- epilogue: bias + guarded float2 stores ----
    const int gid = lane >> 2, qid = lane & 3;
    #pragma unroll
    for (int mt = 0; mt < 4; ++mt) {
        const int oc0 = ocBase + warp_m * 64 + mt * 16 + gid;
        const float bv0 = bias[oc0];
        const float bv1 = bias[oc0 + 8];
        #pragma unroll
        for (int nt = 0; nt < 8; ++nt) {
            const int dh = warp_n * 2 + (nt >> 2);
            const int dw = ((nt >> 1) & 1) * 16 + (nt & 1) * 8 + qid * 2;
            if (w0 + dw < HW) {
                float* dst = out + ((size_t)(img * C_OUT + oc0)) * IMG
                             + (h0 + dh) * HW + (w0 + dw);
                float2 v0, v1;
                v0.x = acc[mt][nt][0] + bv0; v0.y = acc[mt][nt][1] + bv0;
                v1.x = acc[mt][nt][2] + bv1; v1.y = acc[mt][nt][3] + bv1;
                *(float2*)dst = v0;
                *(float2*)(dst + 8 * IMG) = v1;
            }
        }
    }
}

// ---------------- launch ----------------
extern "C" void kernel_launch(void* const* d_in, const int* in_sizes, int n_in,
                              void* d_out, int out_size) {
    const float* x    = (const float*)d_in[0];   // [32,128,56,56]
    const float* w    = (const float*)d_in[1];   // [256,128,3,3]
    const float* bias = (const float*)d_in[2];   // [256]
    float* out = (float*)d_out;                  // [32,256,56,56]

    prep_kernel<<<XBLKS + WBLKS, 256>>>(x, w);

    cudaFuncSetAttribute(conv_mma_kernel,
                         cudaFuncAttributeMaxDynamicSharedMemorySize, SMEM_TOTAL);
    conv_mma_kernel<<<dim3(NIMG * 14, 2), 256, SMEM_TOTAL>>>(bias, out);
}